// round 2
// baseline (speedup 1.0000x reference)
#include <cuda_runtime.h>
#include <math.h>

#define TWO_PI 6.28318530717958647692f

// Scratch (static device allocations are the sanctioned workaround)
__device__ float g_pq[128 * 3 * 2 * 64 * 128];   // [h][v][s(0=cos,1=sin)][c][o], 25.2 MB
__device__ float g_stats[2 * 128 * 2];           // [part][o][sum, sumsq]
__device__ float g_bnp[2 * 128 * 2];             // [part][o][scale, shift]

// ---------------------------------------------------------------------------
__global__ void zero_stats_kernel() {
    int t = threadIdx.x;
    if (t < 512) g_stats[t] = 0.f;
}

// P_v[h][c][o] = sum_u cos(2*pi*h*u/128) * f[u][v][c][o]
// Q_v[h][c][o] = sum_u sin(2*pi*h*u/128) * f[u][v][c][o]
__global__ void precompute_pq_kernel(const float* __restrict__ filters) {
    __shared__ float ct[128], st[128];
    int h = blockIdx.x, t = threadIdx.x;
    if (t < 128) {
        float a = TWO_PI * (float)t * (1.f / 128.f);
        float s_, c_;
        sincosf(a, &s_, &c_);
        ct[t] = c_;
        st[t] = s_;
    }
    __syncthreads();
    for (int e = t; e < 3 * 2 * 64 * 128; e += blockDim.x) {
        int v = e >> 14;          // 0..2
        int s = (e >> 13) & 1;    // 0=cos, 1=sin
        int co = e & 8191;        // c*128 + o
        float acc = 0.f;
        #pragma unroll
        for (int u = 0; u < 3; u++) {
            int a = (h * u) & 127;
            float tr = s ? st[a] : ct[a];
            acc = fmaf(tr, filters[(u * 3 + v) * 8192 + co], acc);
        }
        g_pq[((h * 3 + v) * 2 + s) * 8192 + co] = acc;
    }
}

// ---------------------------------------------------------------------------
// Conv kernel. Grid (128 h-rows, 4 o-chunks of 32), 256 threads.
// Per 8-pixel group:
//   phase A: load X rows (S = r+i rows 0..7, D = i-r rows 8..15) into smem
//            (transposed, padded stride 20 for conflict-free/aligned access),
//            build M[pix][64c][32o] from register-resident P/Q slices.
//   phase B: per-pixel 16x32 GEMM over K=64 with 4x4 register tiles,
//            write raw outputs, accumulate per-channel sum / sumsq.
__global__ __launch_bounds__(256, 2) void conv_kernel(
    const float* __restrict__ xr, const float* __restrict__ xi,
    float* __restrict__ out)
{
    extern __shared__ float smem[];
    float* Ms  = smem;                 // [8][64][32] = 16384 floats
    float* Xt  = smem + 16384;         // [8][64][20] = 10240 floats
    float* ct  = Xt + 10240;           // 128
    float* st  = ct + 128;             // 128
    float* red = st + 128;             // [2][32][2] = 128

    const int h   = blockIdx.x;
    const int och = blockIdx.y;
    const int t   = threadIdx.x;

    if (t < 128) {
        float a = TWO_PI * (float)t * (1.f / 128.f);
        float s_, c_;
        sincosf(a, &s_, &c_);
        ct[t] = c_;
        st[t] = s_;
        red[t] = 0.f;
    }

    // --- register-resident P/Q slice: thread owns (c = 2*cp, 2*cp+1) x 4 o's
    const int cp = t >> 3;            // 0..31
    const int oq = t & 7;             // 0..7
    const int obase = och * 32 + oq * 4;
    float4 P0[2], P1[2], Q1[2], P2[2], Q2[2];
    #pragma unroll
    for (int j = 0; j < 2; j++) {
        int c = 2 * cp + j;
        const float* b = g_pq + (size_t)h * 6 * 8192 + c * 128 + obase;
        P0[j] = *(const float4*)(b + 0 * 8192);   // v=0, cos
        P1[j] = *(const float4*)(b + 2 * 8192);   // v=1, cos
        Q1[j] = *(const float4*)(b + 3 * 8192);   // v=1, sin
        P2[j] = *(const float4*)(b + 4 * 8192);   // v=2, cos
        Q2[j] = *(const float4*)(b + 5 * 8192);   // v=2, sin
    }

    // --- matmul-phase thread mapping
    const int p_ = t >> 5;            // pixel slot 0..7
    const int rg = (t >> 3) & 3;      // row group (rows rg*4..rg*4+3)
    const int og = t & 7;             // o quad

    float bsum[4] = {0.f, 0.f, 0.f, 0.f};
    float bss[4]  = {0.f, 0.f, 0.f, 0.f};

    __syncthreads();

    for (int w0 = 0; w0 < 128; w0 += 8) {
        // ---- phase A: X load + transpose
        #pragma unroll
        for (int k = 0; k < 4; k++) {
            int id  = t + k * 256;          // 0..1023
            int pix = id >> 7;
            int n   = (id >> 4) & 7;
            int c4  = (id & 15) << 2;
            size_t g = ((((size_t)n * 128 + h) * 128) + (w0 + pix)) * 64 + c4;
            float4 r  = *(const float4*)(xr + g);
            float4 im = *(const float4*)(xi + g);
            float* xp = Xt + (pix * 64 + c4) * 20 + n;
            xp[0]      = r.x + im.x;  xp[20]     = r.y + im.y;
            xp[40]     = r.z + im.z;  xp[60]     = r.w + im.w;
            xp[8]      = im.x - r.x;  xp[28]     = im.y - r.y;
            xp[48]     = im.z - r.z;  xp[68]     = im.w - r.w;
        }

        // ---- phase A: build M for 8 pixels from registers
        #pragma unroll
        for (int pix = 0; pix < 8; pix++) {
            int w = w0 + pix;
            float cw1 = ct[w], sw1 = st[w];
            int w2 = (w + w) & 127;
            float cw2 = ct[w2], sw2 = st[w2];
            #pragma unroll
            for (int j = 0; j < 2; j++) {
                int c = 2 * cp + j;
                float4 m;
                m.x = fmaf(cw1, P1[j].x, P0[j].x);
                m.y = fmaf(cw1, P1[j].y, P0[j].y);
                m.z = fmaf(cw1, P1[j].z, P0[j].z);
                m.w = fmaf(cw1, P1[j].w, P0[j].w);
                m.x = fmaf(-sw1, Q1[j].x, m.x);
                m.y = fmaf(-sw1, Q1[j].y, m.y);
                m.z = fmaf(-sw1, Q1[j].z, m.z);
                m.w = fmaf(-sw1, Q1[j].w, m.w);
                m.x = fmaf(cw2, P2[j].x, m.x);
                m.y = fmaf(cw2, P2[j].y, m.y);
                m.z = fmaf(cw2, P2[j].z, m.z);
                m.w = fmaf(cw2, P2[j].w, m.w);
                m.x = fmaf(-sw2, Q2[j].x, m.x);
                m.y = fmaf(-sw2, Q2[j].y, m.y);
                m.z = fmaf(-sw2, Q2[j].z, m.z);
                m.w = fmaf(-sw2, Q2[j].w, m.w);
                *(float4*)(Ms + (pix * 64 + c) * 32 + oq * 4) = m;
            }
        }
        __syncthreads();

        // ---- phase B: 16x32 GEMM per pixel, 4x4 tiles
        float4 acc[4];
        acc[0] = make_float4(0.f, 0.f, 0.f, 0.f);
        acc[1] = acc[0]; acc[2] = acc[0]; acc[3] = acc[0];
        const float* mb = Ms + p_ * 64 * 32 + og * 4;
        const float* xb = Xt + p_ * 64 * 20 + rg * 4;
        #pragma unroll 8
        for (int c = 0; c < 64; c++) {
            float4 m = *(const float4*)(mb + c * 32);
            float4 x = *(const float4*)(xb + c * 20);
            acc[0].x = fmaf(x.x, m.x, acc[0].x);
            acc[0].y = fmaf(x.x, m.y, acc[0].y);
            acc[0].z = fmaf(x.x, m.z, acc[0].z);
            acc[0].w = fmaf(x.x, m.w, acc[0].w);
            acc[1].x = fmaf(x.y, m.x, acc[1].x);
            acc[1].y = fmaf(x.y, m.y, acc[1].y);
            acc[1].z = fmaf(x.y, m.z, acc[1].z);
            acc[1].w = fmaf(x.y, m.w, acc[1].w);
            acc[2].x = fmaf(x.z, m.x, acc[2].x);
            acc[2].y = fmaf(x.z, m.y, acc[2].y);
            acc[2].z = fmaf(x.z, m.z, acc[2].z);
            acc[2].w = fmaf(x.z, m.w, acc[2].w);
            acc[3].x = fmaf(x.w, m.x, acc[3].x);
            acc[3].y = fmaf(x.w, m.y, acc[3].y);
            acc[3].z = fmaf(x.w, m.z, acc[3].z);
            acc[3].w = fmaf(x.w, m.w, acc[3].w);
        }
        int w = w0 + p_;
        int part = rg >> 1;
        int row0 = rg * 4;
        #pragma unroll
        for (int k = 0; k < 4; k++) {
            float4 a = acc[k];
            int n = (row0 + k) & 7;
            size_t oi = (size_t)part * 16777216
                      + ((((size_t)n * 128 + h) * 128) + w) * 128
                      + (och * 32 + og * 4);
            *(float4*)(out + oi) = a;
            bsum[0] += a.x; bsum[1] += a.y; bsum[2] += a.z; bsum[3] += a.w;
            bss[0] = fmaf(a.x, a.x, bss[0]);
            bss[1] = fmaf(a.y, a.y, bss[1]);
            bss[2] = fmaf(a.z, a.z, bss[2]);
            bss[3] = fmaf(a.w, a.w, bss[3]);
        }
        __syncthreads();
    }

    // ---- BN stats reduction: thread-local -> smem atomics -> global atomics
    int part = rg >> 1;
    #pragma unroll
    for (int k = 0; k < 4; k++) {
        int ol = og * 4 + k;
        atomicAdd(&red[(part * 32 + ol) * 2 + 0], bsum[k]);
        atomicAdd(&red[(part * 32 + ol) * 2 + 1], bss[k]);
    }
    __syncthreads();
    if (t < 128) {
        int part2 = t >> 6;
        int ol = (t >> 1) & 31;
        int s = t & 1;
        atomicAdd(&g_stats[(part2 * 128 + och * 32 + ol) * 2 + s], red[t]);
    }
}

// ---------------------------------------------------------------------------
__global__ void bn_finalize_kernel(const float* __restrict__ gr,
                                   const float* __restrict__ br,
                                   const float* __restrict__ gi,
                                   const float* __restrict__ bi) {
    int t = threadIdx.x;             // 256: part = t>>7, o = t&127
    int part = t >> 7, o = t & 127;
    float sum = g_stats[t * 2 + 0];
    float ss  = g_stats[t * 2 + 1];
    const float inv = 1.f / 131072.f;
    float mean = sum * inv;
    float var  = fmaf(-mean, mean, ss * inv);
    float gamma = part ? gi[o] : gr[o];
    float beta  = part ? bi[o] : br[o];
    float a = gamma * rsqrtf(var + 1e-3f);
    float b = fmaf(-mean, a, beta);
    g_bnp[t * 2 + 0] = a;
    g_bnp[t * 2 + 1] = b;
}

__global__ void bn_apply_kernel(float* __restrict__ out) {
    __shared__ float bp[512];
    int t = threadIdx.x;
    bp[t] = g_bnp[t];
    bp[t + 256] = g_bnp[t + 256];
    __syncthreads();
    const int total4 = 33554432 / 4;
    float4* o4 = (float4*)out;
    for (int i = blockIdx.x * blockDim.x + t; i < total4;
         i += gridDim.x * blockDim.x) {
        float4 x = o4[i];
        int e0 = i << 2;
        int o = e0 & 127;
        int part = e0 >> 24;
        const float* b = bp + part * 256 + o * 2;
        float v;
        v = fmaf(b[0], x.x, b[1]); x.x = v >= 0.f ? v : 0.2f * v;
        v = fmaf(b[2], x.y, b[3]); x.y = v >= 0.f ? v : 0.2f * v;
        v = fmaf(b[4], x.z, b[5]); x.z = v >= 0.f ? v : 0.2f * v;
        v = fmaf(b[6], x.w, b[7]); x.w = v >= 0.f ? v : 0.2f * v;
        o4[i] = x;
    }
}

// ---------------------------------------------------------------------------
extern "C" void kernel_launch(void* const* d_in, const int* in_sizes, int n_in,
                              void* d_out, int out_size) {
    const float* xr = (const float*)d_in[0];
    const float* xi = (const float*)d_in[1];
    const float* f  = (const float*)d_in[2];
    const float* gr = (const float*)d_in[3];
    const float* br = (const float*)d_in[4];
    const float* gi = (const float*)d_in[5];
    const float* bi = (const float*)d_in[6];
    float* out = (float*)d_out;

    cudaFuncSetAttribute(conv_kernel,
                         cudaFuncAttributeMaxDynamicSharedMemorySize, 108032);

    zero_stats_kernel<<<1, 512>>>();
    precompute_pq_kernel<<<128, 256>>>(f);
    conv_kernel<<<dim3(128, 4), 256, 108032>>>(xr, xi, out);
    bn_finalize_kernel<<<1, 256>>>(gr, br, gi, bi);
    bn_apply_kernel<<<2048, 256>>>(out);
}

// round 3
// speedup vs baseline: 1.0005x; 1.0005x over previous
#include <cuda_runtime.h>
#include <math.h>

#define TWO_PI 6.28318530717958647692f

// Scratch (static device allocations are the sanctioned workaround)
__device__ float g_pq[128 * 3 * 2 * 64 * 128];   // [h][v][s(0=cos,1=sin)][c][o], 25.2 MB
__device__ float g_stats[2 * 128 * 2];           // [part][o][sum, sumsq]
__device__ float g_bnp[2 * 128 * 2];             // [part][o][scale, shift]

// ---------------------------------------------------------------------------
__global__ void zero_stats_kernel() {
    int t = threadIdx.x;
    if (t < 512) g_stats[t] = 0.f;
}

// P_v[h][c][o] = sum_u cos(2*pi*h*u/128) * f[u][v][c][o]
// Q_v[h][c][o] = sum_u sin(2*pi*h*u/128) * f[u][v][c][o]
__global__ void precompute_pq_kernel(const float* __restrict__ filters) {
    __shared__ float ct[128], st[128];
    int h = blockIdx.x, t = threadIdx.x;
    if (t < 128) {
        float a = TWO_PI * (float)t * (1.f / 128.f);
        float s_, c_;
        sincosf(a, &s_, &c_);
        ct[t] = c_;
        st[t] = s_;
    }
    __syncthreads();
    for (int e = t; e < 3 * 2 * 64 * 128; e += blockDim.x) {
        int v = e >> 14;          // 0..2
        int s = (e >> 13) & 1;    // 0=cos, 1=sin
        int co = e & 8191;        // c*128 + o
        float acc = 0.f;
        #pragma unroll
        for (int u = 0; u < 3; u++) {
            int a = (h * u) & 127;
            float tr = s ? st[a] : ct[a];
            acc = fmaf(tr, filters[(u * 3 + v) * 8192 + co], acc);
        }
        g_pq[((h * 3 + v) * 2 + s) * 8192 + co] = acc;
    }
}

// ---------------------------------------------------------------------------
// Conv kernel. Grid (128 h-rows, 4 o-chunks of 32), 256 threads.
// Per 8-pixel group:
//   phase A: load X rows (S = r+i rows 0..7, D = i-r rows 8..15) into smem
//            (transposed, padded stride 20 for conflict-free/aligned access),
//            build M[pix][64c][32o] from register-resident P/Q slices.
//   phase B: per-pixel 16x32 GEMM over K=64 with 4x4 register tiles,
//            write raw outputs, accumulate per-channel sum / sumsq.
__global__ __launch_bounds__(256, 2) void conv_kernel(
    const float* __restrict__ xr, const float* __restrict__ xi,
    float* __restrict__ out)
{
    extern __shared__ float smem[];
    float* Ms  = smem;                 // [8][64][32] = 16384 floats
    float* Xt  = smem + 16384;         // [8][64][20] = 10240 floats
    float* ct  = Xt + 10240;           // 128
    float* st  = ct + 128;             // 128
    float* red = st + 128;             // [2][32][2] = 128

    const int h   = blockIdx.x;
    const int och = blockIdx.y;
    const int t   = threadIdx.x;

    if (t < 128) {
        float a = TWO_PI * (float)t * (1.f / 128.f);
        float s_, c_;
        sincosf(a, &s_, &c_);
        ct[t] = c_;
        st[t] = s_;
        red[t] = 0.f;
    }

    // --- register-resident P/Q slice: thread owns (c = 2*cp, 2*cp+1) x 4 o's
    const int cp = t >> 3;            // 0..31
    const int oq = t & 7;             // 0..7
    const int obase = och * 32 + oq * 4;
    float4 P0[2], P1[2], Q1[2], P2[2], Q2[2];
    #pragma unroll
    for (int j = 0; j < 2; j++) {
        int c = 2 * cp + j;
        const float* b = g_pq + (size_t)h * 6 * 8192 + c * 128 + obase;
        P0[j] = *(const float4*)(b + 0 * 8192);   // v=0, cos
        P1[j] = *(const float4*)(b + 2 * 8192);   // v=1, cos
        Q1[j] = *(const float4*)(b + 3 * 8192);   // v=1, sin
        P2[j] = *(const float4*)(b + 4 * 8192);   // v=2, cos
        Q2[j] = *(const float4*)(b + 5 * 8192);   // v=2, sin
    }

    // --- matmul-phase thread mapping
    const int p_ = t >> 5;            // pixel slot 0..7
    const int rg = (t >> 3) & 3;      // row group (rows rg*4..rg*4+3)
    const int og = t & 7;             // o quad

    float bsum[4] = {0.f, 0.f, 0.f, 0.f};
    float bss[4]  = {0.f, 0.f, 0.f, 0.f};

    __syncthreads();

    for (int w0 = 0; w0 < 128; w0 += 8) {
        // ---- phase A: X load + transpose
        #pragma unroll
        for (int k = 0; k < 4; k++) {
            int id  = t + k * 256;          // 0..1023
            int pix = id >> 7;
            int n   = (id >> 4) & 7;
            int c4  = (id & 15) << 2;
            size_t g = ((((size_t)n * 128 + h) * 128) + (w0 + pix)) * 64 + c4;
            float4 r  = *(const float4*)(xr + g);
            float4 im = *(const float4*)(xi + g);
            float* xp = Xt + (pix * 64 + c4) * 20 + n;
            xp[0]      = r.x + im.x;  xp[20]     = r.y + im.y;
            xp[40]     = r.z + im.z;  xp[60]     = r.w + im.w;
            xp[8]      = im.x - r.x;  xp[28]     = im.y - r.y;
            xp[48]     = im.z - r.z;  xp[68]     = im.w - r.w;
        }

        // ---- phase A: build M for 8 pixels from registers
        #pragma unroll
        for (int pix = 0; pix < 8; pix++) {
            int w = w0 + pix;
            float cw1 = ct[w], sw1 = st[w];
            int w2 = (w + w) & 127;
            float cw2 = ct[w2], sw2 = st[w2];
            #pragma unroll
            for (int j = 0; j < 2; j++) {
                int c = 2 * cp + j;
                float4 m;
                m.x = fmaf(cw1, P1[j].x, P0[j].x);
                m.y = fmaf(cw1, P1[j].y, P0[j].y);
                m.z = fmaf(cw1, P1[j].z, P0[j].z);
                m.w = fmaf(cw1, P1[j].w, P0[j].w);
                m.x = fmaf(-sw1, Q1[j].x, m.x);
                m.y = fmaf(-sw1, Q1[j].y, m.y);
                m.z = fmaf(-sw1, Q1[j].z, m.z);
                m.w = fmaf(-sw1, Q1[j].w, m.w);
                m.x = fmaf(cw2, P2[j].x, m.x);
                m.y = fmaf(cw2, P2[j].y, m.y);
                m.z = fmaf(cw2, P2[j].z, m.z);
                m.w = fmaf(cw2, P2[j].w, m.w);
                m.x = fmaf(-sw2, Q2[j].x, m.x);
                m.y = fmaf(-sw2, Q2[j].y, m.y);
                m.z = fmaf(-sw2, Q2[j].z, m.z);
                m.w = fmaf(-sw2, Q2[j].w, m.w);
                *(float4*)(Ms + (pix * 64 + c) * 32 + oq * 4) = m;
            }
        }
        __syncthreads();

        // ---- phase B: 16x32 GEMM per pixel, 4x4 tiles
        float4 acc[4];
        acc[0] = make_float4(0.f, 0.f, 0.f, 0.f);
        acc[1] = acc[0]; acc[2] = acc[0]; acc[3] = acc[0];
        const float* mb = Ms + p_ * 64 * 32 + og * 4;
        const float* xb = Xt + p_ * 64 * 20 + rg * 4;
        #pragma unroll 8
        for (int c = 0; c < 64; c++) {
            float4 m = *(const float4*)(mb + c * 32);
            float4 x = *(const float4*)(xb + c * 20);
            acc[0].x = fmaf(x.x, m.x, acc[0].x);
            acc[0].y = fmaf(x.x, m.y, acc[0].y);
            acc[0].z = fmaf(x.x, m.z, acc[0].z);
            acc[0].w = fmaf(x.x, m.w, acc[0].w);
            acc[1].x = fmaf(x.y, m.x, acc[1].x);
            acc[1].y = fmaf(x.y, m.y, acc[1].y);
            acc[1].z = fmaf(x.y, m.z, acc[1].z);
            acc[1].w = fmaf(x.y, m.w, acc[1].w);
            acc[2].x = fmaf(x.z, m.x, acc[2].x);
            acc[2].y = fmaf(x.z, m.y, acc[2].y);
            acc[2].z = fmaf(x.z, m.z, acc[2].z);
            acc[2].w = fmaf(x.z, m.w, acc[2].w);
            acc[3].x = fmaf(x.w, m.x, acc[3].x);
            acc[3].y = fmaf(x.w, m.y, acc[3].y);
            acc[3].z = fmaf(x.w, m.z, acc[3].z);
            acc[3].w = fmaf(x.w, m.w, acc[3].w);
        }
        int w = w0 + p_;
        int part = rg >> 1;
        int row0 = rg * 4;
        #pragma unroll
        for (int k = 0; k < 4; k++) {
            float4 a = acc[k];
            int n = (row0 + k) & 7;
            size_t oi = (size_t)part * 16777216
                      + ((((size_t)n * 128 + h) * 128) + w) * 128
                      + (och * 32 + og * 4);
            *(float4*)(out + oi) = a;
            bsum[0] += a.x; bsum[1] += a.y; bsum[2] += a.z; bsum[3] += a.w;
            bss[0] = fmaf(a.x, a.x, bss[0]);
            bss[1] = fmaf(a.y, a.y, bss[1]);
            bss[2] = fmaf(a.z, a.z, bss[2]);
            bss[3] = fmaf(a.w, a.w, bss[3]);
        }
        __syncthreads();
    }

    // ---- BN stats reduction: thread-local -> smem atomics -> global atomics
    int part = rg >> 1;
    #pragma unroll
    for (int k = 0; k < 4; k++) {
        int ol = og * 4 + k;
        atomicAdd(&red[(part * 32 + ol) * 2 + 0], bsum[k]);
        atomicAdd(&red[(part * 32 + ol) * 2 + 1], bss[k]);
    }
    __syncthreads();
    if (t < 128) {
        int part2 = t >> 6;
        int ol = (t >> 1) & 31;
        int s = t & 1;
        atomicAdd(&g_stats[(part2 * 128 + och * 32 + ol) * 2 + s], red[t]);
    }
}

// ---------------------------------------------------------------------------
__global__ void bn_finalize_kernel(const float* __restrict__ gr,
                                   const float* __restrict__ br,
                                   const float* __restrict__ gi,
                                   const float* __restrict__ bi) {
    int t = threadIdx.x;             // 256: part = t>>7, o = t&127
    int part = t >> 7, o = t & 127;
    float sum = g_stats[t * 2 + 0];
    float ss  = g_stats[t * 2 + 1];
    const float inv = 1.f / 131072.f;
    float mean = sum * inv;
    float var  = fmaf(-mean, mean, ss * inv);
    float gamma = part ? gi[o] : gr[o];
    float beta  = part ? bi[o] : br[o];
    float a = gamma * rsqrtf(var + 1e-3f);
    float b = fmaf(-mean, a, beta);
    g_bnp[t * 2 + 0] = a;
    g_bnp[t * 2 + 1] = b;
}

__global__ void bn_apply_kernel(float* __restrict__ out) {
    __shared__ float bp[512];
    int t = threadIdx.x;
    bp[t] = g_bnp[t];
    bp[t + 256] = g_bnp[t + 256];
    __syncthreads();
    const int total4 = 33554432 / 4;
    float4* o4 = (float4*)out;
    for (int i = blockIdx.x * blockDim.x + t; i < total4;
         i += gridDim.x * blockDim.x) {
        float4 x = o4[i];
        int e0 = i << 2;
        int o = e0 & 127;
        int part = e0 >> 24;
        const float* b = bp + part * 256 + o * 2;
        float v;
        v = fmaf(b[0], x.x, b[1]); x.x = v >= 0.f ? v : 0.2f * v;
        v = fmaf(b[2], x.y, b[3]); x.y = v >= 0.f ? v : 0.2f * v;
        v = fmaf(b[4], x.z, b[5]); x.z = v >= 0.f ? v : 0.2f * v;
        v = fmaf(b[6], x.w, b[7]); x.w = v >= 0.f ? v : 0.2f * v;
        o4[i] = x;
    }
}

// ---------------------------------------------------------------------------
extern "C" void kernel_launch(void* const* d_in, const int* in_sizes, int n_in,
                              void* d_out, int out_size) {
    const float* xr = (const float*)d_in[0];
    const float* xi = (const float*)d_in[1];
    const float* f  = (const float*)d_in[2];
    const float* gr = (const float*)d_in[3];
    const float* br = (const float*)d_in[4];
    const float* gi = (const float*)d_in[5];
    const float* bi = (const float*)d_in[6];
    float* out = (float*)d_out;

    cudaFuncSetAttribute(conv_kernel,
                         cudaFuncAttributeMaxDynamicSharedMemorySize, 108032);

    zero_stats_kernel<<<1, 512>>>();
    precompute_pq_kernel<<<128, 256>>>(f);
    conv_kernel<<<dim3(128, 4), 256, 108032>>>(xr, xi, out);
    bn_finalize_kernel<<<1, 256>>>(gr, br, gi, bi);
    bn_apply_kernel<<<2048, 256>>>(out);
}